// round 8
// baseline (speedup 1.0000x reference)
#include <cuda_runtime.h>
#include <cuda_bf16.h>
#include <cstdint>

#define SENSOR   256
#define IMG_W    1024
#define IMG_H    1024
#define SPP      16
#define NCH      3
#define NBATCH   4
#define HW       (IMG_H * IMG_W)

#define R_MAX    10
#define W_MAX    520
#define TILE_FLOATS (NCH * R_MAX * W_MAX)     // 15600 floats = 62400 B
#define TILE_BYTES  (TILE_FLOATS * 4)

__device__ __forceinline__ float ftanh(float x) {
    float e = __expf(2.0f * x);
    return 1.0f - __fdividef(2.0f, e + 1.0f);
}

__device__ __forceinline__ void cp_async16(uint32_t saddr, const void* gaddr) {
    asm volatile("cp.async.cg.shared.global [%0], [%1], 16;\n"
                 :: "r"(saddr), "l"(gaddr));
}

__global__ __launch_bounds__(128, 3)
void foveated_sensor_kernel(const float* __restrict__ img,
                            const float* __restrict__ t,
                            const float* __restrict__ jitter,
                            float* __restrict__ out)
{
    extern __shared__ float tile[];

    const int p  = blockIdx.x * 128 + threadIdx.x;   // sensor pixel
    const int b  = blockIdx.y;
    const int sw = p & (SENSOR - 1);
    const int sh = p >> 8;

    const float step = 2.0f / (float)SENSOR;
    const float pxv = -1.0f + (float)sw * step;
    const float pyv = -1.0f + (float)sh * step;

    const float tt    = __ldg(t);
    const float s     = tanhf(tt);
    const float inv_s = 1.0f / s;

    const float* __restrict__ imgb = img + (size_t)b * NCH * HW;
    const float2* __restrict__ jit = (const float2*)jitter;

    // ---- CTA-uniform tile bounds (warp is monotonic in pos) ----
    const float posx_lo = -1.0f + (float)((blockIdx.x * 128) & 255) * step;
    const float posx_hi = posx_lo + 128.0f * step;
    const float posy_lo = -1.0f + (float)sh * step;
    const float posy_hi = posy_lo + step;

    float ga = (ftanh(tt * posx_lo) * inv_s + 1.0f) * (0.5f * IMG_W) - 0.5f;
    float gb = (ftanh(tt * posx_hi) * inv_s + 1.0f) * (0.5f * IMG_W) - 0.5f;
    float gxl = fminf(fmaxf(fminf(ga, gb), 0.0f), (float)(IMG_W - 1));
    float gxh = fminf(fmaxf(fmaxf(ga, gb), 0.0f), (float)(IMG_W - 1));

    float gc = (ftanh(tt * posy_lo) * inv_s + 1.0f) * (0.5f * IMG_H) - 0.5f;
    float gd = (ftanh(tt * posy_hi) * inv_s + 1.0f) * (0.5f * IMG_H) - 0.5f;
    float gyl = fminf(fmaxf(fminf(gc, gd), 0.0f), (float)(IMG_H - 1));
    float gyh = fminf(fmaxf(fmaxf(gc, gd), 0.0f), (float)(IMG_H - 1));

    int xlo = max(0, (int)floorf(gxl) - 1);
    int xhi = min(IMG_W - 1, (int)floorf(gxh) + 2);
    int ylo = max(0, (int)floorf(gyl) - 1);
    int yhi = min(IMG_H - 1, (int)floorf(gyh) + 2);
    int xa  = xlo & ~3;
    int Wt  = xhi - xa + 1;
    int W4  = (Wt + 3) & ~3;
    int Rt  = yhi - ylo + 1;

    bool ok = (gxl == gxl) && (gyl == gyl) && (gxh >= gxl) && (gyh >= gyl)
              && (W4 > 0) && (W4 <= W_MAX) && (Rt > 0) && (Rt <= R_MAX);

    float acc0 = 0.f, acc1 = 0.f, acc2 = 0.f, dsum = 0.f;

    if (ok) {
        // ---- dense cp.async load of the footprint, 3 channels ----
        const int n4 = W4 >> 2;
        const int cs = Rt * W4;
        uint32_t sbase = (uint32_t)__cvta_generic_to_shared(tile);

        for (int c = 0; c < NCH; ++c) {
            const float* src = imgb + c * HW + (ylo << 10) + xa;
            for (int r = 0; r < Rt; ++r) {
                const float* srow = src + (r << 10);
                uint32_t sdst = sbase + (uint32_t)((c * cs + r * W4) << 2);
                for (int x4 = threadIdx.x; x4 < n4; x4 += 128)
                    cp_async16(sdst + ((uint32_t)x4 << 4), srow + (x4 << 2));
            }
        }
        asm volatile("cp.async.commit_group;\n cp.async.wait_group 0;\n" ::: "memory");
        __syncthreads();

        const float* __restrict__ T0 = tile;
        const float* __restrict__ T1 = tile + cs;
        const float* __restrict__ T2 = tile + 2 * cs;

#pragma unroll 4
        for (int k = 0; k < SPP; ++k) {
            float2 j = __ldg(&jit[(k << 16) + p]);
            float posx = pxv + j.x * step;
            float posy = pyv + j.y * step;

            float thx = ftanh(tt * posx);
            float thy = ftanh(tt * posy);

            float ddx = tt * (1.0f - thx * thx) * inv_s;
            float ddy = tt * (1.0f - thy * thy) * inv_s;
            float det = ddx * ddy;
            dsum += det;

            float gx = (thx * inv_s + 1.0f) * (0.5f * IMG_W) - 0.5f;
            float gy = (thy * inv_s + 1.0f) * (0.5f * IMG_H) - 0.5f;
            gx = fminf(fmaxf(gx, 0.0f), (float)(IMG_W - 1));
            gy = fminf(fmaxf(gy, 0.0f), (float)(IMG_H - 1));

            float x0f = floorf(gx);
            float y0f = floorf(gy);
            float wx = gx - x0f;
            float wy = gy - y0f;

            int x0 = (int)x0f;
            int y0 = (int)y0f;
            int x1 = min(x0 + 1, IMG_W - 1);
            int y1 = min(y0 + 1, IMG_H - 1);

            int o  = (y0 - ylo) * W4 + (x0 - xa);
            int dx = x1 - x0;
            int dy = (y1 - y0) * W4;

            float a00 = T0[o],      a01 = T0[o + dx];
            float a10 = T0[o + dy], a11 = T0[o + dy + dx];
            float b00 = T1[o],      b01 = T1[o + dx];
            float b10 = T1[o + dy], b11 = T1[o + dy + dx];
            float c00 = T2[o],      c01 = T2[o + dx];
            float c10 = T2[o + dy], c11 = T2[o + dy + dx];

            float top, bot;
            top = fmaf(wx, a01 - a00, a00); bot = fmaf(wx, a11 - a10, a10);
            acc0 = fmaf(fmaf(wy, bot - top, top), det, acc0);
            top = fmaf(wx, b01 - b00, b00); bot = fmaf(wx, b11 - b10, b10);
            acc1 = fmaf(fmaf(wy, bot - top, top), det, acc1);
            top = fmaf(wx, c01 - c00, c00); bot = fmaf(wx, c11 - c10, c10);
            acc2 = fmaf(fmaf(wy, bot - top, top), det, acc2);
        }
    } else {
        // ---- fallback: direct gather (R6 path), for t where tile won't fit ----
#pragma unroll 4
        for (int k = 0; k < SPP; ++k) {
            float2 j = __ldg(&jit[(k << 16) + p]);
            float posx = pxv + j.x * step;
            float posy = pyv + j.y * step;

            float thx = ftanh(tt * posx);
            float thy = ftanh(tt * posy);

            float ddx = tt * (1.0f - thx * thx) * inv_s;
            float ddy = tt * (1.0f - thy * thy) * inv_s;
            float det = ddx * ddy;
            dsum += det;

            float gx = (thx * inv_s + 1.0f) * (0.5f * IMG_W) - 0.5f;
            float gy = (thy * inv_s + 1.0f) * (0.5f * IMG_H) - 0.5f;
            gx = fminf(fmaxf(gx, 0.0f), (float)(IMG_W - 1));
            gy = fminf(fmaxf(gy, 0.0f), (float)(IMG_H - 1));

            float x0f = floorf(gx);
            float y0f = floorf(gy);
            float wx = gx - x0f;
            float wy = gy - y0f;

            int x0 = (int)x0f;
            int y0 = (int)y0f;
            int x1 = min(x0 + 1, IMG_W - 1);
            int y1 = min(y0 + 1, IMG_H - 1);

            const int o00 = (y0 << 10) + x0;
            const int o01 = (y0 << 10) + x1;
            const int o10 = (y1 << 10) + x0;
            const int o11 = (y1 << 10) + x1;

            const float* ip0 = imgb;
            const float* ip1 = imgb + HW;
            const float* ip2 = imgb + 2 * HW;

            float a00 = __ldg(ip0 + o00), a01 = __ldg(ip0 + o01);
            float a10 = __ldg(ip0 + o10), a11 = __ldg(ip0 + o11);
            float b00 = __ldg(ip1 + o00), b01 = __ldg(ip1 + o01);
            float b10 = __ldg(ip1 + o10), b11 = __ldg(ip1 + o11);
            float c00 = __ldg(ip2 + o00), c01 = __ldg(ip2 + o01);
            float c10 = __ldg(ip2 + o10), c11 = __ldg(ip2 + o11);

            float top, bot;
            top = fmaf(wx, a01 - a00, a00); bot = fmaf(wx, a11 - a10, a10);
            acc0 = fmaf(fmaf(wy, bot - top, top), det, acc0);
            top = fmaf(wx, b01 - b00, b00); bot = fmaf(wx, b11 - b10, b10);
            acc1 = fmaf(fmaf(wy, bot - top, top), det, acc1);
            top = fmaf(wx, c01 - c00, c00); bot = fmaf(wx, c11 - c10, c10);
            acc2 = fmaf(fmaf(wy, bot - top, top), det, acc2);
        }
    }

    const float invd = 1.0f / dsum;
    out[((b * NCH + 0) << 16) + p] = acc0 * invd;
    out[((b * NCH + 1) << 16) + p] = acc1 * invd;
    out[((b * NCH + 2) << 16) + p] = acc2 * invd;
}

extern "C" void kernel_launch(void* const* d_in, const int* in_sizes, int n_in,
                              void* d_out, int out_size)
{
    const float* img    = (const float*)d_in[0];
    const float* t      = (const float*)d_in[1];
    const float* jitter = (const float*)d_in[2];
    float* out          = (float*)d_out;

    cudaFuncSetAttribute(foveated_sensor_kernel,
                         cudaFuncAttributeMaxDynamicSharedMemorySize, TILE_BYTES);

    dim3 grid(SENSOR * SENSOR / 128, NBATCH);
    foveated_sensor_kernel<<<grid, 128, TILE_BYTES>>>(img, t, jitter, out);
}

// round 11
// speedup vs baseline: 1.6685x; 1.6685x over previous
#include <cuda_runtime.h>
#include <cuda_bf16.h>

#define SENSOR   256
#define IMG_W    1024
#define IMG_H    1024
#define SPP      16
#define NCH      3
#define NBATCH   4
#define HW       (IMG_H * IMG_W)

// thread layout: warp covers 8 adjacent sensor pixels x 4 spp-groups.
// lane = (g<<3) | q : q = pixel offset 0..7, g = spp group 0..3 (spp k = 4g..4g+3)

__device__ __forceinline__ float ftanh(float x) {
    float e = __expf(2.0f * x);
    return 1.0f - __fdividef(2.0f, e + 1.0f);
}

__global__ __launch_bounds__(256, 5)
void foveated_sensor_kernel(const float* __restrict__ img,
                            const float* __restrict__ t,
                            const float* __restrict__ jitter,
                            float* __restrict__ out)
{
    const int lane = threadIdx.x & 31;
    const int q    = lane & 7;          // pixel offset within warp
    const int g    = lane >> 3;         // spp group 0..3
    const int gw   = blockIdx.x * 8 + (threadIdx.x >> 5);   // global warp id
    const int p    = (gw << 3) + q;     // sensor pixel 0..65535
    const int b    = blockIdx.y;        // batch

    const int sw = p & (SENSOR - 1);
    const int sh = p >> 8;

    const float step = 2.0f / (float)SENSOR;
    const float pxv = -1.0f + (float)sw * step;
    const float pyv = -1.0f + (float)sh * step;

    const float tt    = __ldg(t);
    const float s     = tanhf(tt);
    const float inv_s = 1.0f / s;

    const float* __restrict__ imgb = img + (size_t)b * NCH * HW;
    const float2* __restrict__ jit = (const float2*)jitter;

    float acc0 = 0.f, acc1 = 0.f, acc2 = 0.f, dsum = 0.f;

#pragma unroll
    for (int kk = 0; kk < 4; ++kk) {
        const int k = (g << 2) + kk;
        float2 j = __ldg(&jit[(k << 16) + p]);
        float posx = pxv + j.x * step;
        float posy = pyv + j.y * step;

        float thx = ftanh(tt * posx);
        float thy = ftanh(tt * posy);

        float ddx = tt * (1.0f - thx * thx) * inv_s;
        float ddy = tt * (1.0f - thy * thy) * inv_s;
        float det = ddx * ddy;
        dsum += det;

        float gx = (thx * inv_s + 1.0f) * (0.5f * IMG_W) - 0.5f;
        float gy = (thy * inv_s + 1.0f) * (0.5f * IMG_H) - 0.5f;
        gx = fminf(fmaxf(gx, 0.0f), (float)(IMG_W - 1));
        gy = fminf(fmaxf(gy, 0.0f), (float)(IMG_H - 1));

        float x0f = floorf(gx);
        float y0f = floorf(gy);
        float wx = gx - x0f;
        float wy = gy - y0f;

        int x0 = (int)x0f;
        int y0 = (int)y0f;
        int x1 = min(x0 + 1, IMG_W - 1);
        int y1 = min(y0 + 1, IMG_H - 1);

        const int o00 = (y0 << 10) + x0;
        const int o01 = (y0 << 10) + x1;
        const int o10 = (y1 << 10) + x0;
        const int o11 = (y1 << 10) + x1;

        // channel 0
        float a00 = __ldg(imgb + o00);
        float a01 = __ldg(imgb + o01);
        float a10 = __ldg(imgb + o10);
        float a11 = __ldg(imgb + o11);
        // channel 1
        const float* ip1 = imgb + HW;
        float b00 = __ldg(ip1 + o00);
        float b01 = __ldg(ip1 + o01);
        float b10 = __ldg(ip1 + o10);
        float b11 = __ldg(ip1 + o11);
        // channel 2
        const float* ip2 = imgb + 2 * HW;
        float c00 = __ldg(ip2 + o00);
        float c01 = __ldg(ip2 + o01);
        float c10 = __ldg(ip2 + o10);
        float c11 = __ldg(ip2 + o11);

        float top, bot;
        top = fmaf(wx, a01 - a00, a00); bot = fmaf(wx, a11 - a10, a10);
        acc0 = fmaf(fmaf(wy, bot - top, top), det, acc0);
        top = fmaf(wx, b01 - b00, b00); bot = fmaf(wx, b11 - b10, b10);
        acc1 = fmaf(fmaf(wy, bot - top, top), det, acc1);
        top = fmaf(wx, c01 - c00, c00); bot = fmaf(wx, c11 - c10, c10);
        acc2 = fmaf(fmaf(wy, bot - top, top), det, acc2);
    }

    // combine the 4 spp-groups (lanes l, l^8, l^16, l^24)
    acc0 += __shfl_xor_sync(0xffffffffu, acc0, 8);
    acc1 += __shfl_xor_sync(0xffffffffu, acc1, 8);
    acc2 += __shfl_xor_sync(0xffffffffu, acc2, 8);
    dsum += __shfl_xor_sync(0xffffffffu, dsum, 8);

    acc0 += __shfl_xor_sync(0xffffffffu, acc0, 16);
    acc1 += __shfl_xor_sync(0xffffffffu, acc1, 16);
    acc2 += __shfl_xor_sync(0xffffffffu, acc2, 16);
    dsum += __shfl_xor_sync(0xffffffffu, dsum, 16);

    if (lane < 8) {
        const float invd = 1.0f / dsum;
        out[((b * NCH + 0) << 16) + p] = acc0 * invd;
        out[((b * NCH + 1) << 16) + p] = acc1 * invd;
        out[((b * NCH + 2) << 16) + p] = acc2 * invd;
    }
}

extern "C" void kernel_launch(void* const* d_in, const int* in_sizes, int n_in,
                              void* d_out, int out_size)
{
    const float* img    = (const float*)d_in[0];
    const float* t      = (const float*)d_in[1];
    const float* jitter = (const float*)d_in[2];
    float* out          = (float*)d_out;

    // 8 px per warp, 8 warps per block -> 64 px per block
    dim3 grid(SENSOR * SENSOR / 64, NBATCH);
    foveated_sensor_kernel<<<grid, 256>>>(img, t, jitter, out);
}